// round 13
// baseline (speedup 1.0000x reference)
#include <cuda_runtime.h>
#include <cuda_bf16.h>

#define TRUNC 2048
#define TLEN  2048
#define CAPV  200
#define RPB   4     // rows per block

// ---------------------------------------------------------------------------
// Fused single kernel. One block = (4 rows, 1 channel), 512 threads,
// grid (512, 8) = 4096 blocks (~6.9 waves at 4 blocks/SM co-residency).
// Each thread owns ONE float4 column-group (jb = t*4) across the 4 rows:
// no inner g-loop, 4 independent stores per thread.
// Table build: MUFU-only math, 4096 builds total.
// Fill regions per row i (d = i-j):
//   j > i                 -> 0
//   d > far_thresh        -> constant pattern (no table)
//   else                  -> table lookups (narrow diagonal band)
// ---------------------------------------------------------------------------
__global__ __launch_bounds__(512)
void rem_kernel(const float* __restrict__ eta,
                const float* __restrict__ nu,
                const float* __restrict__ theta,
                float* __restrict__ out)
{
    __shared__ float tab[224];

    const int ch = blockIdx.y;
    const int i0 = blockIdx.x * RPB;
    const int t  = threadIdx.x;
    const float4 zero4 = make_float4(0.f, 0.f, 0.f, 0.f);

    // ---- build table (201 entries), MUFU-only math ----
    if (t <= CAPV) {
        float fl = (float)t;
        float v;
        if (ch < 3) {
            // tanh(x) = 1 - 2/(e^{2x}+1)
            float x   = eta[ch];
            float lam = 1.0f - 2.0f * __frcp_rn(__expf(2.0f * x) + 1.0f);
            if (t == 0) {
                v = 1.0f;
            } else {
                v = exp2f(fl * __log2f(fabsf(lam)));
                if ((t & 1) && lam < 0.0f) v = -v;
            }
        } else if (ch < 6) {
            int h = ch - 3;
            float x  = nu[h];
            float lg  = -__log2f(1.0f + __expf(-x));   // log2(sigmoid)
            float mag = exp2f(fl * lg);
            float ang = theta[h] * fl;
            v = mag * ((h == 2) ? __sinf(ang) : __cosf(ang));
        } else {
            int h = ch - 3;          // 3, 4
            float ang = theta[h] * fl;
            v = (h == 3) ? __cosf(ang) : __sinf(ang);
        }
        tab[t] = v;
    }
    __syncthreads();

    int farth;                    // jb < i - farth  =>  "far" region
    if      (ch == 2) farth = 806;
    else if (ch == 6) farth = 608;
    else              farth = 203;

    const int jb = t << 2;        // this thread's column group (fixed)

    float* __restrict__ chbase =
        out + ((size_t)ch * TRUNC + (size_t)i0) * TLEN;

    #pragma unroll
    for (int r = 0; r < RPB; r++) {
        const int i = i0 + r;
        float4* __restrict__ dst =
            (float4*)(chbase + (size_t)r * TLEN) + t;

        float4 rr;
        if (jb > i) {
            rr = zero4;
        } else if (jb < i - farth) {
            // far region: constants, no table
            if (ch == 2) {
                int im = i & 3;
                rr.x = (im == 0) ? 1.f : 0.f;
                rr.y = (im == 1) ? 1.f : 0.f;
                rr.z = (im == 2) ? 1.f : 0.f;
                rr.w = (im == 3) ? 1.f : 0.f;
            } else if (ch == 6) {
                unsigned r3 = (unsigned)(i - jb) % 3u;
                rr.x = (r3 == 0u) ? 1.f : 0.f;
                rr.y = (r3 == 1u) ? 1.f : 0.f;
                rr.z = (r3 == 2u) ? 1.f : 0.f;
                rr.w = (r3 == 0u) ? 1.f : 0.f;
            } else if (ch == 5 || ch == 7) {
                rr = zero4;
            } else {
                rr = make_float4(1.f, 1.f, 1.f, 1.f);
            }
        } else {
            // diagonal band: table lookups (general path, covers all d >= 0)
            #pragma unroll
            for (int k = 0; k < 4; k++) {
                int d = i - jb - k;
                float v = 0.0f;
                if (d >= 0) {
                    if (ch == 2) {
                        if ((d & 3) == 0) {
                            int dq = d >> 2;
                            v = tab[(dq > CAPV) ? 0 : dq];
                        }
                    } else if (ch == 6) {
                        unsigned ud = (unsigned)d;
                        if (ud % 3u == 0u) {
                            unsigned dq = ud / 3u;
                            v = tab[(dq > CAPV) ? 0 : (int)dq]
                              * tab[(d  > CAPV) ? 0 : d];
                        }
                    } else if (ch == 7) {
                        if (d <= CAPV && (d & 1) == 0)
                            v = tab[d >> 1] * tab[d];
                    } else {
                        v = tab[(d > CAPV) ? 0 : d];
                    }
                    if (d == 0) v -= 1.0f;
                }
                ((float*)&rr)[k] = v;
            }
        }
        *dst = rr;
    }
}

extern "C" void kernel_launch(void* const* d_in, const int* in_sizes, int n_in,
                              void* d_out, int out_size)
{
    const float* eta   = (const float*)d_in[0];
    const float* nu    = (const float*)d_in[1];
    const float* theta = (const float*)d_in[2];
    float* out = (float*)d_out;

    rem_kernel<<<dim3(TRUNC / RPB, 8), 512>>>(eta, nu, theta, out);
}

// round 14
// speedup vs baseline: 1.0833x; 1.0833x over previous
#include <cuda_runtime.h>
#include <cuda_bf16.h>

#define TRUNC 2048
#define TLEN  2048
#define CAPV  200
#define RPB   2     // rows per block

// ---------------------------------------------------------------------------
// Fused single kernel. One block = (2 rows, 1 channel), grid (1024, 8).
// Store path is at the chip LTS cap (~6.2 TB/s); total sits on the DRAM
// write-drain floor (134 MB/replay). Table build uses only MUFU-class math
// and is fully hidden. Fill regions per row i (d = i-j):
//   j > i                 -> 0
//   d > far_thresh        -> constant pattern (no table)
//   else                  -> table lookups (narrow diagonal band)
// ---------------------------------------------------------------------------
__global__ __launch_bounds__(256)
void rem_kernel(const float* __restrict__ eta,
                const float* __restrict__ nu,
                const float* __restrict__ theta,
                float* __restrict__ out)
{
    __shared__ float tab[224];

    const int ch = blockIdx.y;
    const int i0 = blockIdx.x * RPB;
    const int t  = threadIdx.x;
    const float4 zero4 = make_float4(0.f, 0.f, 0.f, 0.f);

    // ---- build table (201 entries), MUFU-only math ----
    if (t <= CAPV) {
        float fl = (float)t;
        float v;
        if (ch < 3) {
            // tanh(x) = 1 - 2/(e^{2x}+1)  (MUFU exp + rcp)
            float x   = eta[ch];
            float lam = 1.0f - 2.0f * __frcp_rn(__expf(2.0f * x) + 1.0f);
            if (t == 0) {
                v = 1.0f;
            } else {
                v = exp2f(fl * __log2f(fabsf(lam)));
                if ((t & 1) && lam < 0.0f) v = -v;
            }
        } else if (ch < 6) {
            int h = ch - 3;
            float x  = nu[h];
            // sigmoid(x)^L = exp2(-L * log2(1 + e^-x))
            float lg  = -__log2f(1.0f + __expf(-x));
            float mag = exp2f(fl * lg);
            float ang = theta[h] * fl;
            v = mag * ((h == 2) ? __sinf(ang) : __cosf(ang));
        } else {
            int h = ch - 3;          // 3, 4
            float ang = theta[h] * fl;
            v = (h == 3) ? __cosf(ang) : __sinf(ang);
        }
        tab[t] = v;
    }
    __syncthreads();

    int farth;                    // groups with jb < i - farth are "far"
    if      (ch == 2) farth = 806;
    else if (ch == 6) farth = 608;
    else              farth = 203;

    #pragma unroll
    for (int r = 0; r < RPB; r++) {
        const int i = i0 + r;
        float4* __restrict__ row4 =
            (float4*)(out + ((size_t)ch * TRUNC + (size_t)i) * TLEN);

        // far-region pattern for this (ch, i): j-independent except ch6
        float4 farv;
        if (ch == 2) {
            int im = i & 3;
            farv.x = (im == 0) ? 1.f : 0.f;
            farv.y = (im == 1) ? 1.f : 0.f;
            farv.z = (im == 2) ? 1.f : 0.f;
            farv.w = (im == 3) ? 1.f : 0.f;
        } else if (ch == 5 || ch == 7) {
            farv = zero4;
        } else {
            farv = make_float4(1.f, 1.f, 1.f, 1.f);
        }

        #pragma unroll
        for (int g = 0; g < 2; g++) {
            int q  = t + (g << 8);
            int jb = q << 2;
            float4 rr;
            if (jb > i) {
                rr = zero4;
            } else if (jb < i - farth) {
                if (ch == 6) {
                    unsigned r3 = (unsigned)(i - jb) % 3u;
                    rr.x = (r3 == 0u) ? 1.f : 0.f;
                    rr.y = (r3 == 1u) ? 1.f : 0.f;
                    rr.z = (r3 == 2u) ? 1.f : 0.f;
                    rr.w = (r3 == 0u) ? 1.f : 0.f;
                } else {
                    rr = farv;
                }
            } else {
                // diagonal band: table lookups (general path, covers all d >= 0)
                #pragma unroll
                for (int k = 0; k < 4; k++) {
                    int d = i - jb - k;
                    float v = 0.0f;
                    if (d >= 0) {
                        if (ch == 2) {
                            if ((d & 3) == 0) {
                                int dq = d >> 2;
                                v = tab[(dq > CAPV) ? 0 : dq];
                            }
                        } else if (ch == 6) {
                            unsigned ud = (unsigned)d;
                            if (ud % 3u == 0u) {
                                unsigned dq = ud / 3u;
                                v = tab[(dq > CAPV) ? 0 : (int)dq]
                                  * tab[(d  > CAPV) ? 0 : d];
                            }
                        } else if (ch == 7) {
                            if (d <= CAPV && (d & 1) == 0)
                                v = tab[d >> 1] * tab[d];
                        } else {
                            v = tab[(d > CAPV) ? 0 : d];
                        }
                        if (d == 0) v -= 1.0f;
                    }
                    ((float*)&rr)[k] = v;
                }
            }
            row4[q] = rr;
        }
    }
}

extern "C" void kernel_launch(void* const* d_in, const int* in_sizes, int n_in,
                              void* d_out, int out_size)
{
    const float* eta   = (const float*)d_in[0];
    const float* nu    = (const float*)d_in[1];
    const float* theta = (const float*)d_in[2];
    float* out = (float*)d_out;

    rem_kernel<<<dim3(TRUNC / RPB, 8), 256>>>(eta, nu, theta, out);
}